// round 3
// baseline (speedup 1.0000x reference)
#include <cuda_runtime.h>
#include <math.h>

// Problem dims
#define BB 64
#define TT 2048
#define DD 128
#define UU 128
#define ROWS (BB*TT)

#define TM 128          // rows per CTA in score kernel
#define NW_PAD 66       // float2 per padded W row in smem (128 cols -> pad 64+2)
#define SCORE_SMEM (UU*NW_PAD*8 + TM*(DD/2)*8)   // 67584 + 65536 = 133120 B

typedef unsigned long long ull;
struct __align__(16) ull2 { ull a, b; };

// ---------------- device scratch (no allocation allowed) ----------------
__device__ __align__(16) float2 g_Wt[UU][DD/2];  // [c][kp]: (.x=W[2kp][c], .y=W[2kp+1][c])
__device__ float g_bias[UU];
__device__ float g_V[UU];
__device__ float g_Vb[1];
__device__ float g_scores[ROWS];

// packed fp32x2 FMA (Blackwell sm_100+)
__device__ __forceinline__ void ffma2(ull& d, ull a, ull b) {
    asm("fma.rn.f32x2 %0, %1, %2, %0;" : "+l"(d) : "l"(a), "l"(b));
}
__device__ __forceinline__ float2 unpack2(ull v) {
    float2 r; asm("mov.b64 {%0,%1}, %2;" : "=f"(r.x), "=f"(r.y) : "l"(v));
    return r;
}

// ---------------- kernel 1: fold weights ----------------
__global__ void prep_kernel(const float* __restrict__ W1, const float* __restrict__ b1,
                            const float* __restrict__ W2, const float* __restrict__ b2,
                            const float* __restrict__ V,  const float* __restrict__ Vb) {
    int idx = blockIdx.x * 256 + threadIdx.x;           // 64 blocks * 256 = 16384
    if (idx < DD * UU) {
        int k = idx >> 7, c = idx & 127;
        float w = W1[idx] + W2[idx];
        if (k & 1) g_Wt[c][k >> 1].y = w;
        else       g_Wt[c][k >> 1].x = w;
    }
    if (idx < UU) {
        g_bias[idx] = b1[idx] + b2[idx];
        g_V[idx]    = V[idx];
    }
    if (idx == 0) g_Vb[0] = Vb[0];
}

// ---------------- kernel 2: scores = V . tanh(xW + b) ----------------
__global__ __launch_bounds__(512) void score_kernel(const float* __restrict__ x) {
    extern __shared__ __align__(16) char smem[];
    float2* ws = (float2*)smem;                                   // [128][NW_PAD]
    float2 (*xs)[DD/2] = (float2(*)[DD/2])(smem + UU*NW_PAD*8);   // [TM][64]

    int tid  = threadIdx.x;
    int row0 = blockIdx.x * TM;

    // stage W (transposed+padded) : 4096 float4 total
    {
        const float4* gw  = (const float4*)g_Wt;
        float4*       wsm = (float4*)ws;
        #pragma unroll
        for (int i = 0; i < 8; i++) {
            int idx = tid + i * 512;        // 0..4095
            int c = idx >> 5, q = idx & 31; // 32 float4 per W row
            wsm[c * (NW_PAD/2) + q] = gw[idx];
        }
    }
    // stage x tile (128 rows x 128 floats) : 4096 float4
    {
        const float4* gx  = (const float4*)(x + (size_t)row0 * DD);
        float4*       xsm = (float4*)xs;
        #pragma unroll
        for (int i = 0; i < 8; i++) xsm[tid + i * 512] = gx[tid + i * 512];
    }
    __syncthreads();

    int tx = tid & 31, ty = tid >> 5;   // ty 0..15
    int r0 = ty * 8;

    ull acc[8][4];
    #pragma unroll
    for (int i = 0; i < 8; i++)
        #pragma unroll
        for (int j = 0; j < 4; j++) acc[i][j] = 0ULL;

    // mainloop: 64 k-pairs, unrolled by 2 (float4-wide smem reads)
    for (int kp = 0; kp < DD/2; kp += 2) {
        ull2 xv[8], wv[4];
        #pragma unroll
        for (int i = 0; i < 8; i++)
            xv[i] = *(const ull2*)&xs[r0 + i][kp];              // warp-broadcast LDS.128
        #pragma unroll
        for (int j = 0; j < 4; j++)
            wv[j] = *(const ull2*)&ws[(tx + 32*j) * NW_PAD + kp]; // conflict-free (pad=66)
        #pragma unroll
        for (int i = 0; i < 8; i++)
            #pragma unroll
            for (int j = 0; j < 4; j++) {
                ffma2(acc[i][j], xv[i].a, wv[j].a);
                ffma2(acc[i][j], xv[i].b, wv[j].b);
            }
    }

    float vb = g_Vb[0];
    float bias[4], vv[4];
    #pragma unroll
    for (int j = 0; j < 4; j++) {
        int c = tx + 32*j;
        bias[j] = g_bias[c];
        vv[j]   = g_V[c];
    }

    #pragma unroll
    for (int i = 0; i < 8; i++) {
        float s = 0.f;
        #pragma unroll
        for (int j = 0; j < 4; j++) {
            float2 p = unpack2(acc[i][j]);
            float z  = p.x + p.y + bias[j];
            s += tanhf(z) * vv[j];
        }
        #pragma unroll
        for (int off = 16; off; off >>= 1)
            s += __shfl_xor_sync(0xffffffffu, s, off);
        if (tx == 0) g_scores[row0 + r0 + i] = s + vb;
    }
}

// ---------------- kernel 3: softmax over T + weighted sum ----------------
__global__ __launch_bounds__(256) void ctx_kernel(const float* __restrict__ x,
                                                  float* __restrict__ out) {
    __shared__ float  se[TT];         // exp(score - max)
    __shared__ float  red[32];
    __shared__ float4 pbuf[8][32];

    int b = blockIdx.x, tid = threadIdx.x;
    int lane = tid & 31, warp = tid >> 5;
    const float* sc = g_scores + (size_t)b * TT;

    // max over T
    float m = -1e30f;
    for (int t = tid; t < TT; t += 256) m = fmaxf(m, sc[t]);
    #pragma unroll
    for (int off = 16; off; off >>= 1) m = fmaxf(m, __shfl_xor_sync(0xffffffffu, m, off));
    if (lane == 0) red[warp] = m;
    __syncthreads();
    m = red[0];
    #pragma unroll
    for (int w = 1; w < 8; w++) m = fmaxf(m, red[w]);

    // exp + sum
    float s = 0.f;
    for (int t = tid; t < TT; t += 256) {
        float e = __expf(sc[t] - m);
        se[t] = e;
        s += e;
    }
    #pragma unroll
    for (int off = 16; off; off >>= 1) s += __shfl_xor_sync(0xffffffffu, s, off);
    __syncthreads();                 // se fully written; red free for reuse
    if (lane == 0) red[warp] = s;
    __syncthreads();
    float Z = 0.f;
    #pragma unroll
    for (int w = 0; w < 8; w++) Z += red[w];
    float inv = 1.f / Z;

    // context[b,:] = (1/Z) * sum_t e[t] * x[b,t,:]
    const float4* xb = (const float4*)(x + (size_t)b * TT * DD);
    float4 acc = make_float4(0.f, 0.f, 0.f, 0.f);
    int t0 = warp * (TT / 8);
    for (int t = t0; t < t0 + TT/8; ++t) {
        float w = se[t];
        float4 v = xb[(size_t)t * 32 + lane];
        acc.x += w * v.x; acc.y += w * v.y; acc.z += w * v.z; acc.w += w * v.w;
    }
    pbuf[warp][lane] = acc;
    __syncthreads();
    if (tid < 32) {
        float4 r = pbuf[0][tid];
        #pragma unroll
        for (int w = 1; w < 8; w++) {
            float4 p = pbuf[w][tid];
            r.x += p.x; r.y += p.y; r.z += p.z; r.w += p.w;
        }
        r.x *= inv; r.y *= inv; r.z *= inv; r.w *= inv;
        ((float4*)(out + (size_t)b * DD))[tid] = r;
    }
}

// ---------------- launch ----------------
extern "C" void kernel_launch(void* const* d_in, const int* in_sizes, int n_in,
                              void* d_out, int out_size) {
    const float* enc = (const float*)d_in[0];
    const float* W1w = (const float*)d_in[1];
    const float* W1b = (const float*)d_in[2];
    const float* W2w = (const float*)d_in[3];
    const float* W2b = (const float*)d_in[4];
    const float* Vw  = (const float*)d_in[5];
    const float* Vb  = (const float*)d_in[6];
    float* out = (float*)d_out;

    prep_kernel<<<64, 256>>>(W1w, W1b, W2w, W2b, Vw, Vb);

    (void)cudaFuncSetAttribute(score_kernel,
                               cudaFuncAttributeMaxDynamicSharedMemorySize, SCORE_SMEM);
    score_kernel<<<ROWS / TM, 512, SCORE_SMEM>>>(enc);

    ctx_kernel<<<BB, 256>>>(enc, out);
}

// round 8
// speedup vs baseline: 1.4905x; 1.4905x over previous
#include <cuda_runtime.h>
#include <cuda_bf16.h>
#include <math.h>
#include <stdint.h>

// Problem dims
#define BB 64
#define TT 2048
#define DD 128
#define UU 128
#define ROWS (BB*TT)
#define TM 128           // rows per CTA in score kernel

// ---------------- device scratch ----------------
// W fragment images for mma.sync m16n8k16 (bf16), per-lane fragment order:
// u32 index = ((ks*16 + nt)*32 + lane)*2 + reg   (ks=k/16, nt=n/8, reg=(k%16)/8)
__device__ __align__(16) uint8_t g_BfragH[32768];
__device__ __align__(16) uint8_t g_BfragL[32768];
__device__ float g_bias[UU];
__device__ float g_V[UU];
__device__ float g_Vb[1];
__device__ float g_scores[ROWS];
__device__ float g_wts[ROWS];
__device__ __align__(16) float g_part[1024][DD];    // 16 chunks x 64 batches

// ---------------- helpers ----------------
__device__ __forceinline__ uint32_t pack2bf(float a, float b) {
    __nv_bfloat162 t = __floats2bfloat162_rn(a, b);
    return reinterpret_cast<uint32_t&>(t);
}
__device__ __forceinline__ void mma_bf16(float* c, const uint4 a, const uint2 b) {
    asm volatile("mma.sync.aligned.m16n8k16.row.col.f32.bf16.bf16.f32 "
        "{%0,%1,%2,%3}, {%4,%5,%6,%7}, {%8,%9}, {%0,%1,%2,%3};"
        : "+f"(c[0]), "+f"(c[1]), "+f"(c[2]), "+f"(c[3])
        : "r"(a.x), "r"(a.y), "r"(a.z), "r"(a.w), "r"(b.x), "r"(b.y));
}
__device__ __forceinline__ float tanh_fast(float z) {
    float e = __expf(2.f * z);
    return 1.f - __fdividef(2.f, e + 1.f);
}

// ---------------- SMEM layout for score kernel ----------------
#define OFF_BIAS 0       // 512B
#define OFF_V    512     // 512B
#define OFF_PART 1024    // 1KB (256 floats)
#define OFF_AH   2048    // 32KB: A_hi fragments, uint4 index (rt*8+ks)*32+lane
#define OFF_AL   34816   // 32KB: A_lo fragments
#define OFF_BH   67584   // 32KB: W_hi fragments (copy of g_BfragH)
#define OFF_BL   100352  // 32KB: W_lo fragments
#define SMEM_TC  133120

// ---------------- kernel 1: fold weights -> bf16 hi/lo fragment images ----------------
__global__ void prep_kernel(const float* __restrict__ W1, const float* __restrict__ b1,
                            const float* __restrict__ W2, const float* __restrict__ b2,
                            const float* __restrict__ V,  const float* __restrict__ Vb) {
    int idx = blockIdx.x * 256 + threadIdx.x;   // 64*256 = 16384 = DD*UU
    if (idx < DD * UU) {
        int k = idx >> 7, n = idx & 127;        // W[k][n]; B operand element (n,k)
        float w = W1[idx] + W2[idx];
        __nv_bfloat16 hi = __float2bfloat16_rn(w);
        float lo = w - __bfloat162float(hi);
        __nv_bfloat16 lob = __float2bfloat16_rn(lo);
        // mma m16n8k16 B-fragment mapping: lane = (n%8)*4 + ((k%8)>>1), reg = (k%16)/8
        int ks = k >> 4, nt = n >> 3, kk = k & 15;
        int lane = (n & 7) * 4 + ((kk & 7) >> 1);
        int reg  = kk >> 3;
        uint32_t i32 = (uint32_t)(((ks * 16 + nt) * 32 + lane) * 2 + reg);
        uint32_t byte = i32 * 4 + (uint32_t)(k & 1) * 2;
        *(__nv_bfloat16*)(g_BfragH + byte) = hi;
        *(__nv_bfloat16*)(g_BfragL + byte) = lob;
    }
    if (idx < UU) {
        g_bias[idx] = b1[idx] + b2[idx];
        g_V[idx]    = V[idx];
    }
    if (idx == 0) g_Vb[0] = Vb[0];
}

// ---------------- kernel 2: scores via mma.sync bf16 3-pass ----------------
__global__ __launch_bounds__(256) void score_mma(const float* __restrict__ x) {
    extern __shared__ __align__(16) char smem[];
    const int tid = threadIdx.x, wid = tid >> 5, lane = tid & 31;
    const int row0 = blockIdx.x * TM;

    float* sbias = (float*)(smem + OFF_BIAS);
    float* sV    = (float*)(smem + OFF_V);
    float* part  = (float*)(smem + OFF_PART);
    uint32_t* AH = (uint32_t*)(smem + OFF_AH);
    uint32_t* AL = (uint32_t*)(smem + OFF_AL);

    if (tid < 128) { sbias[tid] = g_bias[tid]; sV[tid] = g_V[tid]; }

    // stage W fragment images: 2 x 32KB straight copy (uint4)
    {
        const uint4* bh = (const uint4*)g_BfragH;
        const uint4* bl = (const uint4*)g_BfragL;
        uint4* dh = (uint4*)(smem + OFF_BH);
        uint4* dl = (uint4*)(smem + OFF_BL);
        #pragma unroll
        for (int i = 0; i < 8; i++) {
            int q = tid + i * 256;   // 0..2047
            dh[q] = bh[q];
            dl[q] = bl[q];
        }
    }
    // stage A: load x fp32, split to bf16 hi/lo, write in fragment order.
    // thread handles row r = tid>>1, k-half h = tid&1 (k in [64h, 64h+64))
    {
        int r = tid >> 1, h = tid & 1;
        const float4* src = (const float4*)(x + (size_t)(row0 + r) * DD + h * 64);
        int rt = r >> 4, ri = r & 15;
        int jr = (ri >= 8) ? 1 : 0, g = ri & 7;
        #pragma unroll
        for (int i = 0; i < 16; i++) {
            float4 v = src[i];
            int k0 = h * 64 + i * 4;           // pairs at k0 and k0+2
            float h0 = __bfloat162float(__float2bfloat16_rn(v.x));
            float h1 = __bfloat162float(__float2bfloat16_rn(v.y));
            float h2 = __bfloat162float(__float2bfloat16_rn(v.z));
            float h3 = __bfloat162float(__float2bfloat16_rn(v.w));
            uint32_t phi0 = pack2bf(v.x, v.y), phi1 = pack2bf(v.z, v.w);
            uint32_t plo0 = pack2bf(v.x - h0, v.y - h1);
            uint32_t plo1 = pack2bf(v.z - h2, v.w - h3);
            #pragma unroll
            for (int p = 0; p < 2; p++) {
                int k = k0 + p * 2;
                int ks = k >> 4, kk = k & 15;
                int reg  = jr + ((kk >> 3) << 1);            // a0..a3 index
                int ln   = g * 4 + ((kk & 7) >> 1);
                uint32_t a32 = (uint32_t)(((rt * 8 + ks) * 32 + ln) * 4 + reg);
                AH[a32] = p ? phi1 : phi0;
                AL[a32] = p ? plo1 : plo0;
            }
        }
    }
    __syncthreads();

    // warp tiling: 4 row-groups x 2 col-groups
    const int rg = wid & 3;        // rows rg*32 .. +32 (rowtiles rg*2, rg*2+1)
    const int cg = wid >> 2;       // cols cg*64 .. +64 (ntiles cg*8 .. +8)

    float acc[2][8][4];
    #pragma unroll
    for (int j = 0; j < 2; j++)
        #pragma unroll
        for (int t = 0; t < 8; t++)
            #pragma unroll
            for (int e = 0; e < 4; e++) acc[j][t][e] = 0.f;

    const uint4* AfH = (const uint4*)(smem + OFF_AH);
    const uint4* AfL = (const uint4*)(smem + OFF_AL);
    const uint2* BfH = (const uint2*)(smem + OFF_BH);
    const uint2* BfL = (const uint2*)(smem + OFF_BL);

    for (int pass = 0; pass < 3; pass++) {
        const uint4* Af = (pass == 2) ? AfL : AfH;   // (hi,hi), (hi,lo), (lo,hi)
        const uint2* Bf = (pass == 1) ? BfL : BfH;
        #pragma unroll
        for (int ks = 0; ks < 8; ks++) {
            uint4 a0 = Af[((rg * 2 + 0) * 8 + ks) * 32 + lane];
            uint4 a1 = Af[((rg * 2 + 1) * 8 + ks) * 32 + lane];
            #pragma unroll
            for (int nt = 0; nt < 8; nt++) {
                uint2 b = Bf[(ks * 16 + cg * 8 + nt) * 32 + lane];
                mma_bf16(acc[0][nt], a0, b);
                mma_bf16(acc[1][nt], a1, b);
            }
        }
    }

    // epilogue: s[row] = sum_c tanh(z+bias)*V  over this warp's 64 cols
    {
        int q = lane & 3, g = lane >> 2;
        float sum[2][2] = {{0.f, 0.f}, {0.f, 0.f}};   // [rowtile j][row half]
        #pragma unroll
        for (int j = 0; j < 2; j++) {
            #pragma unroll
            for (int nt = 0; nt < 8; nt++) {
                int c0 = cg * 64 + nt * 8 + q * 2;
                float b0 = sbias[c0], b1 = sbias[c0 + 1];
                float v0 = sV[c0],    v1 = sV[c0 + 1];
                sum[j][0] += tanh_fast(acc[j][nt][0] + b0) * v0
                           + tanh_fast(acc[j][nt][1] + b1) * v1;
                sum[j][1] += tanh_fast(acc[j][nt][2] + b0) * v0
                           + tanh_fast(acc[j][nt][3] + b1) * v1;
            }
        }
        #pragma unroll
        for (int j = 0; j < 2; j++)
            #pragma unroll
            for (int hh = 0; hh < 2; hh++) {
                float s = sum[j][hh];
                s += __shfl_xor_sync(0xffffffffu, s, 1);
                s += __shfl_xor_sync(0xffffffffu, s, 2);
                if (q == 0)
                    part[cg * 128 + rg * 32 + j * 16 + hh * 8 + g] = s;
            }
    }
    __syncthreads();
    if (tid < 128)
        g_scores[row0 + tid] = part[tid] + part[128 + tid] + g_Vb[0];
}

// ---------------- kernel 3a: per-batch softmax -> normalized weights ----------------
__global__ __launch_bounds__(256) void stats_kernel() {
    __shared__ float se[TT];
    __shared__ float red[8];
    int b = blockIdx.x, tid = threadIdx.x;
    int lane = tid & 31, warp = tid >> 5;
    const float* sc = g_scores + (size_t)b * TT;

    float m = -1e30f;
    for (int t = tid; t < TT; t += 256) m = fmaxf(m, sc[t]);
    #pragma unroll
    for (int off = 16; off; off >>= 1) m = fmaxf(m, __shfl_xor_sync(0xffffffffu, m, off));
    if (lane == 0) red[warp] = m;
    __syncthreads();
    m = red[0];
    #pragma unroll
    for (int w = 1; w < 8; w++) m = fmaxf(m, red[w]);
    __syncthreads();

    float s = 0.f;
    for (int t = tid; t < TT; t += 256) {
        float e = __expf(sc[t] - m);
        se[t] = e;
        s += e;
    }
    #pragma unroll
    for (int off = 16; off; off >>= 1) s += __shfl_xor_sync(0xffffffffu, s, off);
    if (lane == 0) red[warp] = s;
    __syncthreads();
    float Z = 0.f;
    #pragma unroll
    for (int w = 0; w < 8; w++) Z += red[w];
    float inv = 1.f / Z;

    float* wt = g_wts + (size_t)b * TT;
    for (int t = tid; t < TT; t += 256) wt[t] = se[t] * inv;
}

// ---------------- kernel 3b: partial weighted sums (full-chip) ----------------
__global__ __launch_bounds__(256) void part_kernel(const float* __restrict__ x) {
    __shared__ float4 pbuf[8][32];
    int bid = blockIdx.x;            // 1024
    int b = bid >> 4, chunk = bid & 15;
    int tid = threadIdx.x, lane = tid & 31, warp = tid >> 5;
    int t0 = chunk * 128;

    const float*  wt = g_wts + (size_t)b * TT + t0;
    const float4* xb = (const float4*)(x + ((size_t)b * TT + t0) * DD);

    float4 acc = make_float4(0.f, 0.f, 0.f, 0.f);
    #pragma unroll
    for (int i = 0; i < 16; i++) {
        int t = warp * 16 + i;
        float w = wt[t];
        float4 v = xb[(size_t)t * 32 + lane];
        acc.x += w * v.x; acc.y += w * v.y; acc.z += w * v.z; acc.w += w * v.w;
    }
    pbuf[warp][lane] = acc;
    __syncthreads();
    if (tid < 32) {
        float4 r = pbuf[0][tid];
        #pragma unroll
        for (int w = 1; w < 8; w++) {
            float4 p = pbuf[w][tid];
            r.x += p.x; r.y += p.y; r.z += p.z; r.w += p.w;
        }
        ((float4*)g_part[bid])[tid] = r;
    }
}

// ---------------- kernel 3c: final reduce ----------------
__global__ __launch_bounds__(32) void final_kernel(float* __restrict__ out) {
    int b = blockIdx.x, tid = threadIdx.x;   // 64 blocks x 32 threads
    float4 acc = make_float4(0.f, 0.f, 0.f, 0.f);
    #pragma unroll
    for (int c = 0; c < 16; c++) {
        float4 p = ((const float4*)g_part[b * 16 + c])[tid];
        acc.x += p.x; acc.y += p.y; acc.z += p.z; acc.w += p.w;
    }
    ((float4*)(out + (size_t)b * DD))[tid] = acc;
}

// ---------------- launch ----------------
extern "C" void kernel_launch(void* const* d_in, const int* in_sizes, int n_in,
                              void* d_out, int out_size) {
    const float* enc = (const float*)d_in[0];
    const float* W1w = (const float*)d_in[1];
    const float* W1b = (const float*)d_in[2];
    const float* W2w = (const float*)d_in[3];
    const float* W2b = (const float*)d_in[4];
    const float* Vw  = (const float*)d_in[5];
    const float* Vb  = (const float*)d_in[6];
    float* out = (float*)d_out;

    prep_kernel<<<64, 256>>>(W1w, W1b, W2w, W2b, Vw, Vb);

    (void)cudaFuncSetAttribute(score_mma,
                               cudaFuncAttributeMaxDynamicSharedMemorySize, SMEM_TC);
    score_mma<<<ROWS / TM, 256, SMEM_TC>>>(enc);

    stats_kernel<<<BB, 256>>>();
    part_kernel<<<BB * 16, 256>>>(enc);
    final_kernel<<<BB, 32>>>(out);
}